// round 4
// baseline (speedup 1.0000x reference)
#include <cuda_runtime.h>
#include <cstdint>

#define N_NODES 100000
#define N_EDGES 640000
#define N_FEAT 128
#define N_CLASSES 16

// Scratch (no allocations allowed): ~19.6 MB of __device__ globals.
__device__ float g_y[N_NODES * N_CLASSES];     // x @ W_l^T
__device__ float g_z[N_NODES * N_CLASSES];     // x @ W_r^T + b_l
__device__ float g_acc[N_NODES * N_CLASSES];   // segment sum of g_y over edges
__device__ float g_deg[N_NODES];               // in-degree (float)
__device__ int   g_is64;                       // edge_index dtype flag

// Packed fp32x2 FMA (sm_103a native; ptxas never auto-fuses this)
#define FMA_F32X2(d, a, b, c) \
    asm("fma.rn.f32x2 %0, %1, %2, %3;" : "=l"(d) : "l"(a), "l"(b), "l"(c))

__device__ __forceinline__ unsigned long long pack2(float lo, float hi) {
    unsigned long long r;
    asm("mov.b64 %0, {%1, %2};" : "=l"(r) : "f"(lo), "f"(hi));
    return r;
}
__device__ __forceinline__ float sum2(unsigned long long v) {
    float lo, hi;
    asm("mov.b64 {%0, %1}, %2;" : "=f"(lo), "=f"(hi) : "l"(v));
    return lo + hi;
}

// ---------------------------------------------------------------------------
// Detect whether edge_index buffer is int64 (declared) or int32 (jax x64-off).
// int64 truth: every 8-byte word is an index < 1e5 < 2^32.
// int32 truth: word = lo | (hi<<32), hi ~U[0,1e5) -> >= 2^32 w.p. ~1-1e-5.
// 64 words -> misdetection probability ~(1e-5)^64.
// ---------------------------------------------------------------------------
__global__ void detect_kernel(const unsigned long long* __restrict__ ei) {
    int is64 = 1;
    for (int i = 0; i < 64; i++) {
        if (ei[i] >= (1ULL << 32)) { is64 = 0; break; }
    }
    g_is64 = is64;
}

// ---------------------------------------------------------------------------
// Projection: block of 256 threads handles 256 nodes.
// x rows are staged through smem in 4 chunks of 32 floats with fully
// coalesced 128B loads (vs 16B/line strided direct loads = 8x L1tex waste).
// Tile rows padded to 9 float4 (stride 36 words): STS.128/LDS.128 8-lane
// phases hit banks (base*4 + {0,4,...,28}) mod 32 -> conflict-free.
// Math: packed f32x2 FMAs, weights smem-resident (warp-uniform broadcast).
// Also zero-initializes acc/deg for the edge phase.
// ---------------------------------------------------------------------------
#define CHUNK_F4 8                       // float4s per chunk (32 floats)
#define TILE_STRIDE 9                    // padded row stride in float4

__global__ __launch_bounds__(256) void proj_kernel(
    const float* __restrict__ x,
    const float* __restrict__ Wl,
    const float* __restrict__ bl,
    const float* __restrict__ Wr)
{
    __shared__ float4 sWl[N_CLASSES * (N_FEAT / 4)];   // 8 KB
    __shared__ float4 sWr[N_CLASSES * (N_FEAT / 4)];   // 8 KB
    __shared__ float  sb[N_CLASSES];
    __shared__ float4 tile[256 * TILE_STRIDE];         // 36 KB

    int tid = threadIdx.x;
    const float4* Wl4 = (const float4*)Wl;
    const float4* Wr4 = (const float4*)Wr;
    for (int i = tid; i < N_CLASSES * (N_FEAT / 4); i += 256) {
        sWl[i] = Wl4[i];
        sWr[i] = Wr4[i];
    }
    if (tid < N_CLASSES) sb[tid] = bl[tid];

    int base = blockIdx.x * 256;
    int node = base + tid;
    bool active = (node < N_NODES);

    unsigned long long accl[N_CLASSES];
    unsigned long long accr[N_CLASSES];
#pragma unroll
    for (int c = 0; c < N_CLASSES; c++) { accl[c] = 0ULL; accr[c] = 0ULL; }

    const float4* x4 = (const float4*)x;

    for (int ch = 0; ch < N_FEAT / (4 * CHUNK_F4); ch++) {   // 4 chunks
        __syncthreads();
        // Coalesced stage: flat float4 index f = tid + i*256; n=f/8, j=f%8.
#pragma unroll
        for (int i = 0; i < CHUNK_F4; i++) {
            int f = tid + i * 256;
            int n = f >> 3;
            int j = f & 7;
            int gn = base + n;
            if (gn >= N_NODES) gn = N_NODES - 1;   // clamp (safe read)
            tile[n * TILE_STRIDE + j] =
                x4[(size_t)gn * (N_FEAT / 4) + ch * CHUNK_F4 + j];
        }
        __syncthreads();

#pragma unroll
        for (int j = 0; j < CHUNK_F4; j++) {
            float4 xv = tile[tid * TILE_STRIDE + j];
            unsigned long long xlo = pack2(xv.x, xv.y);
            unsigned long long xhi = pack2(xv.z, xv.w);
            int k = ch * CHUNK_F4 + j;
#pragma unroll
            for (int c = 0; c < N_CLASSES; c++) {
                float4 wl = sWl[c * (N_FEAT / 4) + k];   // uniform -> broadcast
                FMA_F32X2(accl[c], xlo, pack2(wl.x, wl.y), accl[c]);
                FMA_F32X2(accl[c], xhi, pack2(wl.z, wl.w), accl[c]);
                float4 wr = sWr[c * (N_FEAT / 4) + k];
                FMA_F32X2(accr[c], xlo, pack2(wr.x, wr.y), accr[c]);
                FMA_F32X2(accr[c], xhi, pack2(wr.z, wr.w), accr[c]);
            }
        }
    }

    if (active) {
#pragma unroll
        for (int c = 0; c < N_CLASSES; c++) {
            g_y[node * N_CLASSES + c]   = sum2(accl[c]);
            g_z[node * N_CLASSES + c]   = sum2(accr[c]) + sb[c];
            g_acc[node * N_CLASSES + c] = 0.0f;
        }
        g_deg[node] = 0.0f;
    }
}

// ---------------------------------------------------------------------------
// Edge aggregation: 4 threads per edge; thread t -> (edge e=t>>2, quad q=t&3).
// Each thread: one 16B gather from g_y[src], one red.global.add.v4.f32 into
// g_acc[dst]. Vector RED keeps the LTS atomic ALU at ~1 sector-op per 4 adds
// (scalar REDs would make L2 atomic serialization the global bottleneck).
// Both tables (6.4 MB each) are L2-resident.
// ---------------------------------------------------------------------------
__global__ __launch_bounds__(256) void edge_kernel(const void* __restrict__ ei) {
    unsigned t = blockIdx.x * 256u + threadIdx.x;
    if (t >= (unsigned)N_EDGES * 4u) return;
    int e = (int)(t >> 2);
    int q = (int)(t & 3);

    int src, dst;
    if (g_is64) {
        const long long* p = (const long long*)ei;
        src = (int)__ldg(&p[e]);
        dst = (int)__ldg(&p[N_EDGES + e]);
    } else {
        const int* p = (const int*)ei;
        src = __ldg(&p[e]);
        dst = __ldg(&p[N_EDGES + e]);
    }

    const float4* ysrc = (const float4*)(g_y + src * N_CLASSES) + q;
    float4 v = __ldg(ysrc);
    float* d = g_acc + dst * N_CLASSES + q * 4;
    asm volatile("red.global.add.v4.f32 [%0], {%1, %2, %3, %4};"
                 :: "l"(d), "f"(v.x), "f"(v.y), "f"(v.z), "f"(v.w)
                 : "memory");
    if (q == 0) {
        asm volatile("red.global.add.f32 [%0], %1;"
                     :: "l"(g_deg + dst), "f"(1.0f) : "memory");
    }
}

// ---------------------------------------------------------------------------
// Finalize (vectorized): thread t -> node n = t>>2, quad q = t&3.
// out[n][4q..4q+3] = relu(acc/max(deg,1) + z), one float4 ld/ld/st per thread.
// __fdividef (MUFU.RCP path): rel err ~1e-6 << 1e-3 tolerance.
// ---------------------------------------------------------------------------
__global__ __launch_bounds__(256) void fin_kernel(float* __restrict__ out) {
    int t = blockIdx.x * blockDim.x + threadIdx.x;
    if (t >= N_NODES * (N_CLASSES / 4)) return;
    int node = t >> 2;
    float inv = __fdividef(1.0f, fmaxf(g_deg[node], 1.0f));
    const float4* a4 = (const float4*)g_acc + t;
    const float4* z4 = (const float4*)g_z + t;
    float4 a = *a4;
    float4 z = *z4;
    float4 o;
    o.x = fmaxf(fmaf(a.x, inv, z.x), 0.0f);
    o.y = fmaxf(fmaf(a.y, inv, z.y), 0.0f);
    o.z = fmaxf(fmaf(a.z, inv, z.z), 0.0f);
    o.w = fmaxf(fmaf(a.w, inv, z.w), 0.0f);
    ((float4*)out)[t] = o;
}

extern "C" void kernel_launch(void* const* d_in, const int* in_sizes, int n_in,
                              void* d_out, int out_size) {
    const float* x  = (const float*)d_in[0];
    const void*  ei = d_in[1];
    const float* Wl = (const float*)d_in[2];
    const float* bl = (const float*)d_in[3];
    const float* Wr = (const float*)d_in[4];
    float* out = (float*)d_out;

    detect_kernel<<<1, 1>>>((const unsigned long long*)ei);
    proj_kernel<<<(N_NODES + 255) / 256, 256>>>(x, Wl, bl, Wr);
    edge_kernel<<<(N_EDGES * 4 + 255) / 256, 256>>>(ei);
    fin_kernel<<<(N_NODES * (N_CLASSES / 4) + 255) / 256, 256>>>(out);
}

// round 7
// speedup vs baseline: 1.0478x; 1.0478x over previous
#include <cuda_runtime.h>
#include <cstdint>

#define N_NODES 100000
#define N_EDGES 640000
#define N_FEAT 128
#define N_CLASSES 16
#define NB_NODES 391               // ceil(N_NODES/256)

// Scratch (no allocations allowed).
__device__ float4 g_y[N_NODES * 4];        // x @ W_l^T   (16 floats/node)
__device__ float4 g_z[N_NODES * 4];        // x @ W_r^T + b_l
__device__ int    g_cnt[N_NODES];          // histogram -> cursor -> end offset
__device__ int    g_start[N_NODES];        // CSR start offsets
__device__ int    g_blocksum[NB_NODES];    // scan partials
__device__ int    g_csr_src[N_EDGES];      // src id per CSR slot
__device__ int    g_is64;                  // edge_index dtype flag

// Packed fp32x2 FMA (sm_103a native; ptxas never auto-fuses this)
#define FMA_F32X2(d, a, b, c) \
    asm("fma.rn.f32x2 %0, %1, %2, %3;" : "=l"(d) : "l"(a), "l"(b), "l"(c))

__device__ __forceinline__ unsigned long long pack2(float lo, float hi) {
    unsigned long long r;
    asm("mov.b64 %0, {%1, %2};" : "=l"(r) : "f"(lo), "f"(hi));
    return r;
}
__device__ __forceinline__ float sum2(unsigned long long v) {
    float lo, hi;
    asm("mov.b64 {%0, %1}, %2;" : "=f"(lo), "=f"(hi) : "l"(v));
    return lo + hi;
}

// ---------------------------------------------------------------------------
// Init: zero the degree histogram (whole grid) + dtype detect (block 0).
// int64 truth: every 8B word < 1e5 < 2^32. int32 truth: word >= 2^32 w.p.
// ~1-1e-5 per word; 64 words -> misdetection ~(1e-5)^64.
// ---------------------------------------------------------------------------
__global__ __launch_bounds__(256) void init_kernel(const unsigned long long* __restrict__ ei) {
    int i = blockIdx.x * 256 + threadIdx.x;
    if (i < N_NODES) g_cnt[i] = 0;
    if (blockIdx.x == 0 && threadIdx.x == 0) {
        int is64 = 1;
        for (int k = 0; k < 64; k++) {
            if (ei[k] >= (1ULL << 32)) { is64 = 0; break; }
        }
        g_is64 = is64;
    }
}

__device__ __forceinline__ int load_dst(const void* ei, int e) {
    if (g_is64) return (int)__ldg(&((const long long*)ei)[N_EDGES + e]);
    return __ldg(&((const int*)ei)[N_EDGES + e]);
}
__device__ __forceinline__ int load_src(const void* ei, int e) {
    if (g_is64) return (int)__ldg(&((const long long*)ei)[e]);
    return __ldg(&((const int*)ei)[e]);
}

// ---------------------------------------------------------------------------
// Projection + fused in-degree histogram.
// Block of 256 threads handles 256 nodes (coalesced smem staging of x,
// pad-9 float4 rows, weights smem-resident, packed f32x2 FMAs) AND
// histograms a disjoint ~1637-edge slice of edge_index. The histogram's
// LSU/LTS atomic traffic overlaps the FMA-issue-bound projection loop
// (complementary pipes), hiding it almost entirely.
// ---------------------------------------------------------------------------
#define CHUNK_F4 8
#define TILE_STRIDE 9
#define EDGES_PER_BLOCK ((N_EDGES + NB_NODES - 1) / NB_NODES)   // 1637

__global__ __launch_bounds__(256) void proj_kernel(
    const float* __restrict__ x,
    const float* __restrict__ Wl,
    const float* __restrict__ bl,
    const float* __restrict__ Wr,
    const void* __restrict__ ei)
{
    __shared__ float4 sWl[N_CLASSES * (N_FEAT / 4)];   // 8 KB
    __shared__ float4 sWr[N_CLASSES * (N_FEAT / 4)];   // 8 KB
    __shared__ float  sb[N_CLASSES];
    __shared__ float4 tile[256 * TILE_STRIDE];         // 36 KB

    int tid = threadIdx.x;
    const float4* Wl4 = (const float4*)Wl;
    const float4* Wr4 = (const float4*)Wr;
    for (int i = tid; i < N_CLASSES * (N_FEAT / 4); i += 256) {
        sWl[i] = Wl4[i];
        sWr[i] = Wr4[i];
    }
    if (tid < N_CLASSES) sb[tid] = bl[tid];

    // Fused histogram slice (independent of the FMA work below; issued
    // first so the atomics drain while the projection computes).
    {
        int e0 = blockIdx.x * EDGES_PER_BLOCK;
        int e1 = min(e0 + EDGES_PER_BLOCK, N_EDGES);
        for (int e = e0 + tid; e < e1; e += 256) {
            atomicAdd(&g_cnt[load_dst(ei, e)], 1);
        }
    }

    int base = blockIdx.x * 256;
    int node = base + tid;
    bool active = (node < N_NODES);

    unsigned long long accl[N_CLASSES];
    unsigned long long accr[N_CLASSES];
#pragma unroll
    for (int c = 0; c < N_CLASSES; c++) { accl[c] = 0ULL; accr[c] = 0ULL; }

    const float4* x4 = (const float4*)x;

    for (int ch = 0; ch < N_FEAT / (4 * CHUNK_F4); ch++) {
        __syncthreads();
#pragma unroll
        for (int i = 0; i < CHUNK_F4; i++) {
            int f = tid + i * 256;
            int n = f >> 3;
            int j = f & 7;
            int gn = base + n;
            if (gn >= N_NODES) gn = N_NODES - 1;
            tile[n * TILE_STRIDE + j] =
                x4[(size_t)gn * (N_FEAT / 4) + ch * CHUNK_F4 + j];
        }
        __syncthreads();

#pragma unroll
        for (int j = 0; j < CHUNK_F4; j++) {
            float4 xv = tile[tid * TILE_STRIDE + j];
            unsigned long long xlo = pack2(xv.x, xv.y);
            unsigned long long xhi = pack2(xv.z, xv.w);
            int k = ch * CHUNK_F4 + j;
#pragma unroll
            for (int c = 0; c < N_CLASSES; c++) {
                float4 wl = sWl[c * (N_FEAT / 4) + k];
                FMA_F32X2(accl[c], xlo, pack2(wl.x, wl.y), accl[c]);
                FMA_F32X2(accl[c], xhi, pack2(wl.z, wl.w), accl[c]);
                float4 wr = sWr[c * (N_FEAT / 4) + k];
                FMA_F32X2(accr[c], xlo, pack2(wr.x, wr.y), accr[c]);
                FMA_F32X2(accr[c], xhi, pack2(wr.z, wr.w), accr[c]);
            }
        }
    }

    if (active) {
#pragma unroll
        for (int c4 = 0; c4 < 4; c4++) {
            float4 vy, vz;
            vy.x = sum2(accl[c4 * 4 + 0]);
            vy.y = sum2(accl[c4 * 4 + 1]);
            vy.z = sum2(accl[c4 * 4 + 2]);
            vy.w = sum2(accl[c4 * 4 + 3]);
            vz.x = sum2(accr[c4 * 4 + 0]) + sb[c4 * 4 + 0];
            vz.y = sum2(accr[c4 * 4 + 1]) + sb[c4 * 4 + 1];
            vz.z = sum2(accr[c4 * 4 + 2]) + sb[c4 * 4 + 2];
            vz.w = sum2(accr[c4 * 4 + 3]) + sb[c4 * 4 + 3];
            g_y[node * 4 + c4] = vy;
            g_z[node * 4 + c4] = vz;
        }
    }
}

// ---------------------------------------------------------------------------
// CSR build, step 2a: per-block exclusive scan; block sums to g_blocksum.
// ---------------------------------------------------------------------------
__global__ __launch_bounds__(256) void scan_local_kernel() {
    __shared__ int s[256];
    int tid = threadIdx.x;
    int i = blockIdx.x * 256 + tid;
    int v = (i < N_NODES) ? g_cnt[i] : 0;
    s[tid] = v;
    __syncthreads();
#pragma unroll
    for (int off = 1; off < 256; off <<= 1) {
        int t = (tid >= off) ? s[tid - off] : 0;
        __syncthreads();
        s[tid] += t;
        __syncthreads();
    }
    if (i < N_NODES) g_start[i] = s[tid] - v;     // exclusive (local)
    if (tid == 255) g_blocksum[blockIdx.x] = s[255];
}

// ---------------------------------------------------------------------------
// CSR build, step 2b: single-block exclusive scan of the 391 block sums.
// ---------------------------------------------------------------------------
__global__ __launch_bounds__(512) void scan_block_kernel() {
    __shared__ int s[512];
    int tid = threadIdx.x;
    int v = (tid < NB_NODES) ? g_blocksum[tid] : 0;
    s[tid] = v;
    __syncthreads();
#pragma unroll
    for (int off = 1; off < 512; off <<= 1) {
        int t = (tid >= off) ? s[tid - off] : 0;
        __syncthreads();
        s[tid] += t;
        __syncthreads();
    }
    if (tid < NB_NODES) g_blocksum[tid] = s[tid] - v;   // exclusive
}

// ---------------------------------------------------------------------------
// CSR build, step 2c: add block offsets; init scatter cursors.
// ---------------------------------------------------------------------------
__global__ __launch_bounds__(256) void add_off_kernel() {
    int i = blockIdx.x * 256 + threadIdx.x;
    if (i >= N_NODES) return;
    int st = g_start[i] + g_blocksum[i >> 8];
    g_start[i] = st;
    g_cnt[i] = st;                                  // cursor
}

// ---------------------------------------------------------------------------
// CSR build, step 3: scatter src ids into per-dst slots (2 edges/thread).
// After this, g_cnt[i] == end offset of node i's list.
// ---------------------------------------------------------------------------
__global__ __launch_bounds__(256) void scatter_kernel(const void* __restrict__ ei) {
    int e = (blockIdx.x * 256 + threadIdx.x) * 2;
    if (e >= N_EDGES) return;
#pragma unroll
    for (int u = 0; u < 2; u++) {
        int ee = e + u;
        if (ee >= N_EDGES) break;
        int src = load_src(ei, ee);
        int dst = load_dst(ei, ee);
        int pos = atomicAdd(&g_cnt[dst], 1);
        g_csr_src[pos] = src;
    }
}

// ---------------------------------------------------------------------------
// Gather + finalize (fused): 4 threads per node, one float4 quad each.
// Index load is a 4-lane same-address broadcast; the 4 quads of g_y[src]
// form one contiguous 64B segment per edge. Register accumulation (zero
// float atomics), then out = relu(acc/max(deg,1) + z), deg = end - start.
// ---------------------------------------------------------------------------
__global__ __launch_bounds__(256) void gather_fin_kernel(float* __restrict__ out) {
    int t = blockIdx.x * 256 + threadIdx.x;
    if (t >= N_NODES * 4) return;
    int node = t >> 2;
    int q = t & 3;

    int s = g_start[node];
    int e = g_cnt[node];

    float4 a = make_float4(0.f, 0.f, 0.f, 0.f);
    for (int i = s; i < e; i++) {
        int src = __ldg(&g_csr_src[i]);
        float4 v = g_y[src * 4 + q];
        a.x += v.x; a.y += v.y; a.z += v.z; a.w += v.w;
    }

    float inv = __fdividef(1.0f, fmaxf((float)(e - s), 1.0f));
    float4 z = g_z[node * 4 + q];
    float4 o;
    o.x = fmaxf(fmaf(a.x, inv, z.x), 0.0f);
    o.y = fmaxf(fmaf(a.y, inv, z.y), 0.0f);
    o.z = fmaxf(fmaf(a.z, inv, z.z), 0.0f);
    o.w = fmaxf(fmaf(a.w, inv, z.w), 0.0f);
    ((float4*)out)[t] = o;
}

extern "C" void kernel_launch(void* const* d_in, const int* in_sizes, int n_in,
                              void* d_out, int out_size) {
    const float* x  = (const float*)d_in[0];
    const void*  ei = d_in[1];
    const float* Wl = (const float*)d_in[2];
    const float* bl = (const float*)d_in[3];
    const float* Wr = (const float*)d_in[4];
    float* out = (float*)d_out;

    init_kernel<<<NB_NODES, 256>>>((const unsigned long long*)ei);
    proj_kernel<<<NB_NODES, 256>>>(x, Wl, bl, Wr, ei);
    scan_local_kernel<<<NB_NODES, 256>>>();
    scan_block_kernel<<<1, 512>>>();
    add_off_kernel<<<NB_NODES, 256>>>();
    scatter_kernel<<<(N_EDGES / 2 + 255) / 256, 256>>>(ei);
    gather_fin_kernel<<<(N_NODES * 4 + 255) / 256, 256>>>(out);
}